// round 5
// baseline (speedup 1.0000x reference)
#include <cuda_runtime.h>
#include <math.h>

// GraphSAGE 3-layer, N=100000 nodes, E=3200000 edges, D: 64 -> 64 -> 32 -> 1
// Project-before-aggregate + per-call CSR build + warp-per-node gather.
// NOTE: edge_index is int32 (JAX silently downgrades int64 without x64 mode).
// All __device__ scratch arrays referenced ONLY from device code.

#define NMAX 100000
#define EMAX 3200000

__device__ __align__(16) float g_p[NMAX * 64];    // projected features
__device__ __align__(16) float g_agg[NMAX * 64];  // aggregated means
__device__ __align__(16) float g_h1[NMAX * 64];   // layer-1 hidden
__device__ float g_p3[NMAX];                      // h2 @ W3l
__device__ float g_r3[NMAX];                      // h2 @ W3r (self term)
__device__ float g_inv[NMAX];                     // 1 / max(deg, 1)
__device__ int   g_deg[NMAX];
__device__ int   g_start[NMAX];
__device__ int   g_fill[NMAX];
__device__ int   g_csr[EMAX];                     // src ids bucketed by dst

// ---------------- CSR build ----------------

__global__ void zero_deg_kernel(int N) {
    int i = blockIdx.x * blockDim.x + threadIdx.x;
    if (i < N) g_deg[i] = 0;
}

__global__ void hist_kernel(const int* __restrict__ dst, int E) {
    int e = blockIdx.x * blockDim.x + threadIdx.x;
    if (e < E) atomicAdd(&g_deg[dst[e]], 1);
}

// Single block, 1024 threads: exclusive scan of degrees -> start; also inv and fill=0.
__global__ void scan_kernel(int N) {
    __shared__ int ssum[1024];
    int tid = threadIdx.x;
    int per = (N + 1023) / 1024;
    int lo = tid * per;
    int hi = min(lo + per, N);
    int s = 0;
    for (int i = lo; i < hi; i++) s += g_deg[i];
    ssum[tid] = s;
    __syncthreads();
    for (int off = 1; off < 1024; off <<= 1) {
        int v = 0;
        if (tid >= off) v = ssum[tid - off];
        __syncthreads();
        if (tid >= off) ssum[tid] += v;
        __syncthreads();
    }
    int base = (tid == 0) ? 0 : ssum[tid - 1];
    for (int i = lo; i < hi; i++) {
        g_start[i] = base;
        int d = g_deg[i];
        g_inv[i] = 1.0f / fmaxf((float)d, 1.0f);
        g_fill[i] = 0;
        base += d;
    }
}

__global__ void place_kernel(const int* __restrict__ src,
                             const int* __restrict__ dst, int E) {
    int e = blockIdx.x * blockDim.x + threadIdx.x;
    if (e >= E) return;
    int d = dst[e];
    int pos = g_start[d] + atomicAdd(&g_fill[d], 1);
    g_csr[pos] = src[e];
}

// ---------------- dense projections / combines ----------------

// g_p[node, o] = sum_k x[node, k] * W1l[k, o]
__global__ void proj1_kernel(const float* __restrict__ x,
                             const float* __restrict__ W, int N) {
    __shared__ float sW[64 * 64];
    for (int i = threadIdx.x; i < 64 * 64; i += blockDim.x) sW[i] = W[i];
    __syncthreads();
    int t = blockIdx.x * blockDim.x + threadIdx.x;
    int node = t >> 6;
    int o = t & 63;
    if (node >= N) return;
    const float* xr = x + (long long)node * 64;
    float acc = 0.f;
#pragma unroll
    for (int k = 0; k < 64; k++) acc = fmaf(xr[k], sW[k * 64 + o], acc);
    g_p[t] = acc;
}

// g_h1[node, o] = relu(g_agg[node, o] + b1[o] + sum_k x[node, k] * W1r[k, o])
__global__ void combine1_kernel(const float* __restrict__ b,
                                const float* __restrict__ x,
                                const float* __restrict__ Wr, int N) {
    __shared__ float sW[64 * 64];
    __shared__ float sb[64];
    for (int i = threadIdx.x; i < 64 * 64; i += blockDim.x) sW[i] = Wr[i];
    if (threadIdx.x < 64) sb[threadIdx.x] = b[threadIdx.x];
    __syncthreads();
    int t = blockIdx.x * blockDim.x + threadIdx.x;
    int node = t >> 6;
    int o = t & 63;
    if (node >= N) return;
    const float* xr = x + (long long)node * 64;
    float acc = g_agg[t] + sb[o];
#pragma unroll
    for (int k = 0; k < 64; k++) acc = fmaf(xr[k], sW[k * 64 + o], acc);
    g_h1[t] = fmaxf(acc, 0.f);
}

// g_p[node, o] = sum_k g_h1[node, k] * W2l[k, o]   (64 -> 32)
__global__ void proj2_kernel(const float* __restrict__ W, int N) {
    __shared__ float sW[64 * 32];
    for (int i = threadIdx.x; i < 64 * 32; i += blockDim.x) sW[i] = W[i];
    __syncthreads();
    int t = blockIdx.x * blockDim.x + threadIdx.x;
    int node = t >> 5;
    int o = t & 31;
    if (node >= N) return;
    const float* hr = g_h1 + (long long)node * 64;
    float acc = 0.f;
#pragma unroll
    for (int k = 0; k < 64; k++) acc = fmaf(hr[k], sW[k * 32 + o], acc);
    g_p[t] = acc;
}

// Layer-2 combine fused with both layer-3 projections. One warp per node.
__global__ void combine2_fused_kernel(const float* __restrict__ b2,
                                      const float* __restrict__ W2r,
                                      const float* __restrict__ W3l,
                                      const float* __restrict__ W3r, int N) {
    __shared__ float sW[64 * 32];
    __shared__ float sb[32], s3l[32], s3r[32];
    for (int i = threadIdx.x; i < 64 * 32; i += blockDim.x) sW[i] = W2r[i];
    if (threadIdx.x < 32) {
        sb[threadIdx.x] = b2[threadIdx.x];
        s3l[threadIdx.x] = W3l[threadIdx.x];
        s3r[threadIdx.x] = W3r[threadIdx.x];
    }
    __syncthreads();
    int g = blockIdx.x * blockDim.x + threadIdx.x;
    int node = g >> 5;
    int lane = g & 31;
    if (node >= N) return;
    const float* hr = g_h1 + (long long)node * 64;
    float acc = g_agg[(long long)node * 32 + lane] + sb[lane];
#pragma unroll
    for (int k = 0; k < 64; k++) acc = fmaf(hr[k], sW[k * 32 + lane], acc);
    float h2 = fmaxf(acc, 0.f);
    float a = h2 * s3l[lane];
    float r = h2 * s3r[lane];
#pragma unroll
    for (int off = 16; off; off >>= 1) {
        a += __shfl_xor_sync(0xffffffffu, a, off);
        r += __shfl_xor_sync(0xffffffffu, r, off);
    }
    if (lane == 0) {
        g_p3[node] = a;
        g_r3[node] = r;
    }
}

// ---------------- CSR gather aggregation (mean) ----------------

// d=64: one warp per node, each lane owns 2 consecutive floats (float2).
__global__ void gather64_kernel(int N) {
    int g = blockIdx.x * blockDim.x + threadIdx.x;
    int node = g >> 5;
    int lane = g & 31;
    if (node >= N) return;
    int s0 = g_start[node];
    int d = g_deg[node];
    float ax = 0.f, ay = 0.f;
#pragma unroll 4
    for (int j = 0; j < d; j++) {
        int s = g_csr[s0 + j];
        float2 v = ((const float2*)(g_p + (long long)s * 64))[lane];
        ax += v.x;
        ay += v.y;
    }
    float iv = g_inv[node];
    ((float2*)(g_agg + (long long)node * 64))[lane] = make_float2(ax * iv, ay * iv);
}

// d=32: one warp per node, one float per lane.
__global__ void gather32_kernel(int N) {
    int g = blockIdx.x * blockDim.x + threadIdx.x;
    int node = g >> 5;
    int lane = g & 31;
    if (node >= N) return;
    int s0 = g_start[node];
    int d = g_deg[node];
    float acc = 0.f;
#pragma unroll 4
    for (int j = 0; j < d; j++) {
        int s = g_csr[s0 + j];
        acc += g_p[(long long)s * 32 + lane];
    }
    g_agg[(long long)node * 32 + lane] = acc * g_inv[node];
}

// d=1: one warp per node, lanes parallel over edges; fused final sigmoid.
__global__ void gather1_final_kernel(const float* __restrict__ b3,
                                     float* __restrict__ out, int N) {
    int g = blockIdx.x * blockDim.x + threadIdx.x;
    int node = g >> 5;
    int lane = g & 31;
    if (node >= N) return;
    int s0 = g_start[node];
    int d = g_deg[node];
    float acc = 0.f;
    for (int j = lane; j < d; j += 32) acc += g_p3[g_csr[s0 + j]];
#pragma unroll
    for (int off = 16; off; off >>= 1) acc += __shfl_xor_sync(0xffffffffu, acc, off);
    if (lane == 0) {
        float v = acc * g_inv[node] + b3[0] + g_r3[node];
        out[node] = 1.0f / (1.0f + expf(-v));
    }
}

// ---------------- launch ----------------

extern "C" void kernel_launch(void* const* d_in, const int* in_sizes, int n_in,
                              void* d_out, int out_size) {
    const float* x   = (const float*)d_in[0];
    const int*   ei  = (const int*)d_in[1];   // int32! (JAX x64 disabled)
    const float* W1l = (const float*)d_in[2];
    const float* b1  = (const float*)d_in[3];
    const float* W1r = (const float*)d_in[4];
    const float* W2l = (const float*)d_in[5];
    const float* b2  = (const float*)d_in[6];
    const float* W2r = (const float*)d_in[7];
    const float* W3l = (const float*)d_in[8];
    const float* b3  = (const float*)d_in[9];
    const float* W3r = (const float*)d_in[10];
    float* out = (float*)d_out;

    int N = in_sizes[0] / 64;
    int E = in_sizes[1] / 2;
    const int* src = ei;
    const int* dst = ei + E;

    const int TB = 256;
    auto blocks = [](long long n, int tb) { return (int)((n + tb - 1) / tb); };

    // CSR build (reused by all 3 layers)
    zero_deg_kernel<<<blocks(N, TB), TB>>>(N);
    hist_kernel<<<blocks(E, TB), TB>>>(dst, E);
    scan_kernel<<<1, 1024>>>(N);
    place_kernel<<<blocks(E, TB), TB>>>(src, dst, E);

    // ---- layer 1 ----
    proj1_kernel<<<blocks((long long)N * 64, TB), TB>>>(x, W1l, N);
    gather64_kernel<<<blocks((long long)N * 32, TB), TB>>>(N);
    combine1_kernel<<<blocks((long long)N * 64, TB), TB>>>(b1, x, W1r, N);

    // ---- layer 2 (project 64->32 before aggregating) ----
    proj2_kernel<<<blocks((long long)N * 32, TB), TB>>>(W2l, N);
    gather32_kernel<<<blocks((long long)N * 32, TB), TB>>>(N);
    combine2_fused_kernel<<<blocks((long long)N * 32, TB), TB>>>(b2, W2r, W3l, W3r, N);

    // ---- layer 3 (scalar per node, fused sigmoid) ----
    gather1_final_kernel<<<blocks((long long)N * 32, TB), TB>>>(b3, out, N);
}

// round 7
// speedup vs baseline: 1.0414x; 1.0414x over previous
#include <cuda_runtime.h>
#include <cuda_fp16.h>
#include <math.h>

// GraphSAGE 3-layer, N=100000, E=3200000, D: 64 -> 64 -> 32 -> 1
// CSR-gather aggregation with fp16 scatter sources (fp32 accumulate),
// project-before-aggregate for layer 2/3, fused epilogues.
// __device__ scratch referenced ONLY from device code.

#define NMAX 100000
#define EMAX 3200000

__device__ __align__(16) float   g_agg[NMAX * 64];  // aggregated means (fp32)
__device__ __align__(16) float   g_h1[NMAX * 64];   // layer-1 hidden
__device__ __align__(16) __half2 g_xh[NMAX * 32];   // x in fp16 (64 per node)
__device__ __align__(16) __half2 g_p2[NMAX * 16];   // projected h1@W2l in fp16 (32 per node)
__device__ float g_p3[NMAX];                        // h2 @ W3l
__device__ float g_r3[NMAX];                        // h2 @ W3r (self term)
__device__ float g_inv[NMAX];                       // 1 / max(deg, 1)
__device__ int   g_deg[NMAX];
__device__ int   g_start[NMAX];
__device__ int   g_fill[NMAX];
__device__ int   g_csr[EMAX];                       // src ids bucketed by dst

// ---------------- CSR build ----------------

__global__ void zero_deg_kernel(int N) {
    int i = blockIdx.x * blockDim.x + threadIdx.x;
    if (i < N) g_deg[i] = 0;
}

__global__ void hist_kernel(const int* __restrict__ dst, int E) {
    int e = blockIdx.x * blockDim.x + threadIdx.x;
    if (e < E) atomicAdd(&g_deg[dst[e]], 1);
}

// Single block, 1024 threads: exclusive scan of degrees -> start; also inv, fill=0.
__global__ void scan_kernel(int N) {
    __shared__ int ssum[1024];
    int tid = threadIdx.x;
    int per = (N + 1023) / 1024;
    int lo = tid * per;
    int hi = min(lo + per, N);
    int s = 0;
    for (int i = lo; i < hi; i++) s += g_deg[i];
    ssum[tid] = s;
    __syncthreads();
    for (int off = 1; off < 1024; off <<= 1) {
        int v = 0;
        if (tid >= off) v = ssum[tid - off];
        __syncthreads();
        if (tid >= off) ssum[tid] += v;
        __syncthreads();
    }
    int base = (tid == 0) ? 0 : ssum[tid - 1];
    for (int i = lo; i < hi; i++) {
        g_start[i] = base;
        int d = g_deg[i];
        g_inv[i] = 1.0f / fmaxf((float)d, 1.0f);
        g_fill[i] = 0;
        base += d;
    }
}

__global__ void place_kernel(const int* __restrict__ src,
                             const int* __restrict__ dst, int E) {
    int e = blockIdx.x * blockDim.x + threadIdx.x;
    if (e >= E) return;
    int d = dst[e];
    int pos = g_start[d] + atomicAdd(&g_fill[d], 1);
    g_csr[pos] = src[e];
}

// ---------------- fp16 conversion ----------------

__global__ void convert_x_kernel(const float* __restrict__ x, int N) {
    int t = blockIdx.x * blockDim.x + threadIdx.x;  // N*32 half2 slots
    if (t >= N * 32) return;
    float2 v = ((const float2*)x)[t];
    g_xh[t] = __floats2half2_rn(v.x, v.y);
}

// ---------------- gathers (mean, fp16 sources, fp32 accumulate) ----------------

// 64-d: one warp per node, lane owns one half2 (cols 2*lane, 2*lane+1). Row = 128B.
__global__ void gather64h_kernel(int N) {
    int g = blockIdx.x * blockDim.x + threadIdx.x;
    int node = g >> 5;
    int lane = g & 31;
    if (node >= N) return;
    int s0 = g_start[node];
    int d = g_deg[node];
    float ax = 0.f, ay = 0.f;
    int j = 0;
    for (; j + 4 <= d; j += 4) {
        int s0i = g_csr[s0 + j];
        int s1i = g_csr[s0 + j + 1];
        int s2i = g_csr[s0 + j + 2];
        int s3i = g_csr[s0 + j + 3];
        __half2 v0 = g_xh[s0i * 32 + lane];
        __half2 v1 = g_xh[s1i * 32 + lane];
        __half2 v2 = g_xh[s2i * 32 + lane];
        __half2 v3 = g_xh[s3i * 32 + lane];
        float2 f0 = __half22float2(v0);
        float2 f1 = __half22float2(v1);
        float2 f2 = __half22float2(v2);
        float2 f3 = __half22float2(v3);
        ax += (f0.x + f1.x) + (f2.x + f3.x);
        ay += (f0.y + f1.y) + (f2.y + f3.y);
    }
    for (; j < d; j++) {
        float2 f = __half22float2(g_xh[g_csr[s0 + j] * 32 + lane]);
        ax += f.x;
        ay += f.y;
    }
    float iv = g_inv[node];
    ((float2*)g_agg)[node * 32 + lane] = make_float2(ax * iv, ay * iv);
}

// 32-d: two nodes per warp, 16 lanes per node, lane owns one half2. Row = 64B.
__global__ void gather32h_kernel(int N) {
    int g = blockIdx.x * blockDim.x + threadIdx.x;
    int node = g >> 4;
    int lane = g & 15;
    if (node >= N) return;
    int s0 = g_start[node];
    int d = g_deg[node];
    float ax = 0.f, ay = 0.f;
    int j = 0;
    for (; j + 4 <= d; j += 4) {
        int s0i = g_csr[s0 + j];
        int s1i = g_csr[s0 + j + 1];
        int s2i = g_csr[s0 + j + 2];
        int s3i = g_csr[s0 + j + 3];
        __half2 v0 = g_p2[s0i * 16 + lane];
        __half2 v1 = g_p2[s1i * 16 + lane];
        __half2 v2 = g_p2[s2i * 16 + lane];
        __half2 v3 = g_p2[s3i * 16 + lane];
        float2 f0 = __half22float2(v0);
        float2 f1 = __half22float2(v1);
        float2 f2 = __half22float2(v2);
        float2 f3 = __half22float2(v3);
        ax += (f0.x + f1.x) + (f2.x + f3.x);
        ay += (f0.y + f1.y) + (f2.y + f3.y);
    }
    for (; j < d; j++) {
        float2 f = __half22float2(g_p2[g_csr[s0 + j] * 16 + lane]);
        ax += f.x;
        ay += f.y;
    }
    float iv = g_inv[node];
    ((float2*)g_agg)[node * 16 + lane] = make_float2(ax * iv, ay * iv);
}

// ---------------- dense combines / projections ----------------

// h1[node,o] = relu(mean[node,:]@W1l[:,o] + b1[o] + x[node,:]@W1r[:,o])
__global__ void combine1_kernel(const float* __restrict__ Wl,
                                const float* __restrict__ b,
                                const float* __restrict__ x,
                                const float* __restrict__ Wr, int N) {
    __shared__ float sWl[64 * 64];
    __shared__ float sWr[64 * 64];
    __shared__ float sb[64];
    for (int i = threadIdx.x; i < 64 * 64; i += blockDim.x) {
        sWl[i] = Wl[i];
        sWr[i] = Wr[i];
    }
    if (threadIdx.x < 64) sb[threadIdx.x] = b[threadIdx.x];
    __syncthreads();
    int t = blockIdx.x * blockDim.x + threadIdx.x;
    int node = t >> 6;
    int o = t & 63;
    if (node >= N) return;
    const float* xr = x + (long long)node * 64;
    const float* mr = g_agg + (long long)node * 64;
    float acc = sb[o];
#pragma unroll
    for (int k = 0; k < 64; k++) {
        acc = fmaf(mr[k], sWl[k * 64 + o], acc);
        acc = fmaf(xr[k], sWr[k * 64 + o], acc);
    }
    g_h1[t] = fmaxf(acc, 0.f);
}

// p2[node,o] = fp16(sum_k h1[node,k] * W2l[k,o])   (64 -> 32)
__global__ void proj2h_kernel(const float* __restrict__ W, int N) {
    __shared__ float sW[64 * 32];
    for (int i = threadIdx.x; i < 64 * 32; i += blockDim.x) sW[i] = W[i];
    __syncthreads();
    int t = blockIdx.x * blockDim.x + threadIdx.x;  // node*32 + o
    int node = t >> 5;
    int o = t & 31;
    if (node >= N) return;
    const float* hr = g_h1 + (long long)node * 64;
    float acc = 0.f;
#pragma unroll
    for (int k = 0; k < 64; k++) acc = fmaf(hr[k], sW[k * 32 + o], acc);
    ((__half*)g_p2)[t] = __float2half_rn(acc);
}

// Layer-2 combine fused with both layer-3 projections. One warp per node.
__global__ void combine2_fused_kernel(const float* __restrict__ b2,
                                      const float* __restrict__ W2r,
                                      const float* __restrict__ W3l,
                                      const float* __restrict__ W3r, int N) {
    __shared__ float sW[64 * 32];
    __shared__ float sb[32], s3l[32], s3r[32];
    for (int i = threadIdx.x; i < 64 * 32; i += blockDim.x) sW[i] = W2r[i];
    if (threadIdx.x < 32) {
        sb[threadIdx.x] = b2[threadIdx.x];
        s3l[threadIdx.x] = W3l[threadIdx.x];
        s3r[threadIdx.x] = W3r[threadIdx.x];
    }
    __syncthreads();
    int g = blockIdx.x * blockDim.x + threadIdx.x;
    int node = g >> 5;
    int lane = g & 31;
    if (node >= N) return;
    const float* hr = g_h1 + (long long)node * 64;
    float acc = g_agg[(long long)node * 32 + lane] + sb[lane];
#pragma unroll
    for (int k = 0; k < 64; k++) acc = fmaf(hr[k], sW[k * 32 + lane], acc);
    float h2 = fmaxf(acc, 0.f);
    float a = h2 * s3l[lane];
    float r = h2 * s3r[lane];
#pragma unroll
    for (int off = 16; off; off >>= 1) {
        a += __shfl_xor_sync(0xffffffffu, a, off);
        r += __shfl_xor_sync(0xffffffffu, r, off);
    }
    if (lane == 0) {
        g_p3[node] = a;
        g_r3[node] = r;
    }
}

// Final: one warp per node, lanes parallel over edges; fused sigmoid.
__global__ void gather1_final_kernel(const float* __restrict__ b3,
                                     float* __restrict__ out, int N) {
    int g = blockIdx.x * blockDim.x + threadIdx.x;
    int node = g >> 5;
    int lane = g & 31;
    if (node >= N) return;
    int s0 = g_start[node];
    int d = g_deg[node];
    float acc = 0.f;
    for (int j = lane; j < d; j += 32) acc += g_p3[g_csr[s0 + j]];
#pragma unroll
    for (int off = 16; off; off >>= 1) acc += __shfl_xor_sync(0xffffffffu, acc, off);
    if (lane == 0) {
        float v = acc * g_inv[node] + b3[0] + g_r3[node];
        out[node] = 1.0f / (1.0f + expf(-v));
    }
}

// ---------------- launch ----------------

extern "C" void kernel_launch(void* const* d_in, const int* in_sizes, int n_in,
                              void* d_out, int out_size) {
    const float* x   = (const float*)d_in[0];
    const int*   ei  = (const int*)d_in[1];   // int32 (JAX x64 disabled)
    const float* W1l = (const float*)d_in[2];
    const float* b1  = (const float*)d_in[3];
    const float* W1r = (const float*)d_in[4];
    const float* W2l = (const float*)d_in[5];
    const float* b2  = (const float*)d_in[6];
    const float* W2r = (const float*)d_in[7];
    const float* W3l = (const float*)d_in[8];
    const float* b3  = (const float*)d_in[9];
    const float* W3r = (const float*)d_in[10];
    float* out = (float*)d_out;

    int N = in_sizes[0] / 64;
    int E = in_sizes[1] / 2;
    const int* src = ei;
    const int* dst = ei + E;

    const int TB = 256;
    auto blocks = [](long long n, int tb) { return (int)((n + tb - 1) / tb); };

    // CSR build (reused by all 3 layers); convert x to fp16 concurrently.
    zero_deg_kernel<<<blocks(N, TB), TB>>>(N);
    hist_kernel<<<blocks(E, TB), TB>>>(dst, E);
    convert_x_kernel<<<blocks((long long)N * 32, TB), TB>>>(x, N);
    scan_kernel<<<1, 1024>>>(N);
    place_kernel<<<blocks(E, TB), TB>>>(src, dst, E);

    // ---- layer 1: gather raw x (fp16), combine does both GEMMs ----
    gather64h_kernel<<<blocks((long long)N * 32, TB), TB>>>(N);
    combine1_kernel<<<blocks((long long)N * 64, TB), TB>>>(W1l, b1, x, W1r, N);

    // ---- layer 2: project 64->32 (fp16), gather, fused combine + layer-3 proj ----
    proj2h_kernel<<<blocks((long long)N * 32, TB), TB>>>(W2l, N);
    gather32h_kernel<<<blocks((long long)N * 16, TB), TB>>>(N);
    combine2_fused_kernel<<<blocks((long long)N * 32, TB), TB>>>(b2, W2r, W3l, W3r, N);

    // ---- layer 3: scalar gather + sigmoid ----
    gather1_final_kernel<<<blocks((long long)N * 32, TB), TB>>>(b3, out, N);
}

// round 8
// speedup vs baseline: 1.4555x; 1.3976x over previous
#include <cuda_runtime.h>
#include <cuda_fp16.h>
#include <math.h>

// GraphSAGE 3-layer, N=100000, E=3200000, D: 64 -> 64 -> 32 -> 1
// CSR-gather aggregation with fp16 scatter sources (fp32 accumulate),
// project-before-aggregate for layer 2/3, fused epilogues.
// R8: replaced 218us single-block scan with 3-phase parallel scan.

#define NMAX 100000
#define EMAX 3200000
#define SCAN_TB 1024
#define NBLK ((NMAX + SCAN_TB - 1) / SCAN_TB)

__device__ __align__(16) float   g_agg[NMAX * 64];  // aggregated means (fp32)
__device__ __align__(16) float   g_h1[NMAX * 64];   // layer-1 hidden
__device__ __align__(16) __half2 g_xh[NMAX * 32];   // x in fp16 (64 per node)
__device__ __align__(16) __half2 g_p2[NMAX * 16];   // projected h1@W2l in fp16 (32 per node)
__device__ float g_p3[NMAX];                        // h2 @ W3l
__device__ float g_r3[NMAX];                        // h2 @ W3r (self term)
__device__ float g_inv[NMAX];                       // 1 / max(deg, 1)
__device__ int   g_deg[NMAX];
__device__ int   g_start[NMAX];
__device__ int   g_fill[NMAX];
__device__ int   g_bsum[NBLK + 1];
__device__ int   g_csr[EMAX];                       // src ids bucketed by dst

// ---------------- CSR build ----------------

__global__ void zero_deg_kernel(int N) {
    int i = blockIdx.x * blockDim.x + threadIdx.x;
    if (i < N) g_deg[i] = 0;
}

__global__ void hist_kernel(const int* __restrict__ dst, int E) {
    int e = blockIdx.x * blockDim.x + threadIdx.x;
    if (e < E) atomicAdd(&g_deg[dst[e]], 1);
}

// Phase 1: per-block sum of degrees.
__global__ void blocksum_kernel(int N) {
    __shared__ int sred[SCAN_TB];
    int i = blockIdx.x * SCAN_TB + threadIdx.x;
    int d = (i < N) ? g_deg[i] : 0;
    sred[threadIdx.x] = d;
    __syncthreads();
    for (int off = SCAN_TB / 2; off > 0; off >>= 1) {
        if (threadIdx.x < off) sred[threadIdx.x] += sred[threadIdx.x + off];
        __syncthreads();
    }
    if (threadIdx.x == 0) g_bsum[blockIdx.x] = sred[0];
}

// Phase 2: exclusive scan of NBLK block sums (tiny, single block).
__global__ void scan_bsums_kernel(int nb) {
    if (threadIdx.x == 0) {
        int acc = 0;
        for (int i = 0; i < nb; i++) {
            int v = g_bsum[i];
            g_bsum[i] = acc;
            acc += v;
        }
    }
}

// Phase 3: per-block exclusive scan of degrees + block offset -> start/inv/fill.
__global__ void starts_kernel(int N) {
    __shared__ int stmp[SCAN_TB];
    int i = blockIdx.x * SCAN_TB + threadIdx.x;
    int d = (i < N) ? g_deg[i] : 0;
    stmp[threadIdx.x] = d;
    __syncthreads();
    for (int off = 1; off < SCAN_TB; off <<= 1) {
        int v = (threadIdx.x >= off) ? stmp[threadIdx.x - off] : 0;
        __syncthreads();
        stmp[threadIdx.x] += v;
        __syncthreads();
    }
    if (i < N) {
        int excl = stmp[threadIdx.x] - d + g_bsum[blockIdx.x];
        g_start[i] = excl;
        g_inv[i] = 1.0f / fmaxf((float)d, 1.0f);
        g_fill[i] = 0;
    }
}

__global__ void place_kernel(const int* __restrict__ src,
                             const int* __restrict__ dst, int E) {
    int e = blockIdx.x * blockDim.x + threadIdx.x;
    if (e >= E) return;
    int d = dst[e];
    int pos = g_start[d] + atomicAdd(&g_fill[d], 1);
    g_csr[pos] = src[e];
}

// ---------------- fp16 conversion ----------------

__global__ void convert_x_kernel(const float* __restrict__ x, int N) {
    int t = blockIdx.x * blockDim.x + threadIdx.x;  // N*32 half2 slots
    if (t >= N * 32) return;
    float2 v = ((const float2*)x)[t];
    g_xh[t] = __floats2half2_rn(v.x, v.y);
}

// ---------------- gathers (mean, fp16 sources, fp32 accumulate) ----------------

// 64-d: one warp per node, lane owns one half2 (cols 2*lane, 2*lane+1). Row = 128B.
__global__ void gather64h_kernel(int N) {
    int g = blockIdx.x * blockDim.x + threadIdx.x;
    int node = g >> 5;
    int lane = g & 31;
    if (node >= N) return;
    int s0 = g_start[node];
    int d = g_deg[node];
    float ax = 0.f, ay = 0.f;
    int j = 0;
    for (; j + 4 <= d; j += 4) {
        int s0i = g_csr[s0 + j];
        int s1i = g_csr[s0 + j + 1];
        int s2i = g_csr[s0 + j + 2];
        int s3i = g_csr[s0 + j + 3];
        __half2 v0 = g_xh[s0i * 32 + lane];
        __half2 v1 = g_xh[s1i * 32 + lane];
        __half2 v2 = g_xh[s2i * 32 + lane];
        __half2 v3 = g_xh[s3i * 32 + lane];
        float2 f0 = __half22float2(v0);
        float2 f1 = __half22float2(v1);
        float2 f2 = __half22float2(v2);
        float2 f3 = __half22float2(v3);
        ax += (f0.x + f1.x) + (f2.x + f3.x);
        ay += (f0.y + f1.y) + (f2.y + f3.y);
    }
    for (; j < d; j++) {
        float2 f = __half22float2(g_xh[g_csr[s0 + j] * 32 + lane]);
        ax += f.x;
        ay += f.y;
    }
    float iv = g_inv[node];
    ((float2*)g_agg)[node * 32 + lane] = make_float2(ax * iv, ay * iv);
}

// 32-d: two nodes per warp, 16 lanes per node, lane owns one half2. Row = 64B.
__global__ void gather32h_kernel(int N) {
    int g = blockIdx.x * blockDim.x + threadIdx.x;
    int node = g >> 4;
    int lane = g & 15;
    if (node >= N) return;
    int s0 = g_start[node];
    int d = g_deg[node];
    float ax = 0.f, ay = 0.f;
    int j = 0;
    for (; j + 4 <= d; j += 4) {
        int s0i = g_csr[s0 + j];
        int s1i = g_csr[s0 + j + 1];
        int s2i = g_csr[s0 + j + 2];
        int s3i = g_csr[s0 + j + 3];
        __half2 v0 = g_p2[s0i * 16 + lane];
        __half2 v1 = g_p2[s1i * 16 + lane];
        __half2 v2 = g_p2[s2i * 16 + lane];
        __half2 v3 = g_p2[s3i * 16 + lane];
        float2 f0 = __half22float2(v0);
        float2 f1 = __half22float2(v1);
        float2 f2 = __half22float2(v2);
        float2 f3 = __half22float2(v3);
        ax += (f0.x + f1.x) + (f2.x + f3.x);
        ay += (f0.y + f1.y) + (f2.y + f3.y);
    }
    for (; j < d; j++) {
        float2 f = __half22float2(g_p2[g_csr[s0 + j] * 16 + lane]);
        ax += f.x;
        ay += f.y;
    }
    float iv = g_inv[node];
    ((float2*)g_agg)[node * 16 + lane] = make_float2(ax * iv, ay * iv);
}

// ---------------- dense combines / projections ----------------

// h1[node,o] = relu(mean[node,:]@W1l[:,o] + b1[o] + x[node,:]@W1r[:,o])
__global__ void combine1_kernel(const float* __restrict__ Wl,
                                const float* __restrict__ b,
                                const float* __restrict__ x,
                                const float* __restrict__ Wr, int N) {
    __shared__ float sWl[64 * 64];
    __shared__ float sWr[64 * 64];
    __shared__ float sb[64];
    for (int i = threadIdx.x; i < 64 * 64; i += blockDim.x) {
        sWl[i] = Wl[i];
        sWr[i] = Wr[i];
    }
    if (threadIdx.x < 64) sb[threadIdx.x] = b[threadIdx.x];
    __syncthreads();
    int t = blockIdx.x * blockDim.x + threadIdx.x;
    int node = t >> 6;
    int o = t & 63;
    if (node >= N) return;
    const float* xr = x + (long long)node * 64;
    const float* mr = g_agg + (long long)node * 64;
    float acc = sb[o];
#pragma unroll
    for (int k = 0; k < 64; k++) {
        acc = fmaf(mr[k], sWl[k * 64 + o], acc);
        acc = fmaf(xr[k], sWr[k * 64 + o], acc);
    }
    g_h1[t] = fmaxf(acc, 0.f);
}

// p2[node,o] = fp16(sum_k h1[node,k] * W2l[k,o])   (64 -> 32)
__global__ void proj2h_kernel(const float* __restrict__ W, int N) {
    __shared__ float sW[64 * 32];
    for (int i = threadIdx.x; i < 64 * 32; i += blockDim.x) sW[i] = W[i];
    __syncthreads();
    int t = blockIdx.x * blockDim.x + threadIdx.x;  // node*32 + o
    int node = t >> 5;
    int o = t & 31;
    if (node >= N) return;
    const float* hr = g_h1 + (long long)node * 64;
    float acc = 0.f;
#pragma unroll
    for (int k = 0; k < 64; k++) acc = fmaf(hr[k], sW[k * 32 + o], acc);
    ((__half*)g_p2)[t] = __float2half_rn(acc);
}

// Layer-2 combine fused with both layer-3 projections. One warp per node.
__global__ void combine2_fused_kernel(const float* __restrict__ b2,
                                      const float* __restrict__ W2r,
                                      const float* __restrict__ W3l,
                                      const float* __restrict__ W3r, int N) {
    __shared__ float sW[64 * 32];
    __shared__ float sb[32], s3l[32], s3r[32];
    for (int i = threadIdx.x; i < 64 * 32; i += blockDim.x) sW[i] = W2r[i];
    if (threadIdx.x < 32) {
        sb[threadIdx.x] = b2[threadIdx.x];
        s3l[threadIdx.x] = W3l[threadIdx.x];
        s3r[threadIdx.x] = W3r[threadIdx.x];
    }
    __syncthreads();
    int g = blockIdx.x * blockDim.x + threadIdx.x;
    int node = g >> 5;
    int lane = g & 31;
    if (node >= N) return;
    const float* hr = g_h1 + (long long)node * 64;
    float acc = g_agg[(long long)node * 32 + lane] + sb[lane];
#pragma unroll
    for (int k = 0; k < 64; k++) acc = fmaf(hr[k], sW[k * 32 + lane], acc);
    float h2 = fmaxf(acc, 0.f);
    float a = h2 * s3l[lane];
    float r = h2 * s3r[lane];
#pragma unroll
    for (int off = 16; off; off >>= 1) {
        a += __shfl_xor_sync(0xffffffffu, a, off);
        r += __shfl_xor_sync(0xffffffffu, r, off);
    }
    if (lane == 0) {
        g_p3[node] = a;
        g_r3[node] = r;
    }
}

// Final: one warp per node, lanes parallel over edges; fused sigmoid.
__global__ void gather1_final_kernel(const float* __restrict__ b3,
                                     float* __restrict__ out, int N) {
    int g = blockIdx.x * blockDim.x + threadIdx.x;
    int node = g >> 5;
    int lane = g & 31;
    if (node >= N) return;
    int s0 = g_start[node];
    int d = g_deg[node];
    float acc = 0.f;
    for (int j = lane; j < d; j += 32) acc += g_p3[g_csr[s0 + j]];
#pragma unroll
    for (int off = 16; off; off >>= 1) acc += __shfl_xor_sync(0xffffffffu, acc, off);
    if (lane == 0) {
        float v = acc * g_inv[node] + b3[0] + g_r3[node];
        out[node] = 1.0f / (1.0f + expf(-v));
    }
}

// ---------------- launch ----------------

extern "C" void kernel_launch(void* const* d_in, const int* in_sizes, int n_in,
                              void* d_out, int out_size) {
    const float* x   = (const float*)d_in[0];
    const int*   ei  = (const int*)d_in[1];   // int32 (JAX x64 disabled)
    const float* W1l = (const float*)d_in[2];
    const float* b1  = (const float*)d_in[3];
    const float* W1r = (const float*)d_in[4];
    const float* W2l = (const float*)d_in[5];
    const float* b2  = (const float*)d_in[6];
    const float* W2r = (const float*)d_in[7];
    const float* W3l = (const float*)d_in[8];
    const float* b3  = (const float*)d_in[9];
    const float* W3r = (const float*)d_in[10];
    float* out = (float*)d_out;

    int N = in_sizes[0] / 64;
    int E = in_sizes[1] / 2;
    const int* src = ei;
    const int* dst = ei + E;

    const int TB = 256;
    auto blocks = [](long long n, int tb) { return (int)((n + tb - 1) / tb); };
    int nb = (N + SCAN_TB - 1) / SCAN_TB;

    // CSR build (reused by all 3 layers); convert x to fp16 concurrently.
    zero_deg_kernel<<<blocks(N, TB), TB>>>(N);
    hist_kernel<<<blocks(E, TB), TB>>>(dst, E);
    convert_x_kernel<<<blocks((long long)N * 32, TB), TB>>>(x, N);
    blocksum_kernel<<<nb, SCAN_TB>>>(N);
    scan_bsums_kernel<<<1, 32>>>(nb);
    starts_kernel<<<nb, SCAN_TB>>>(N);
    place_kernel<<<blocks(E, TB), TB>>>(src, dst, E);

    // ---- layer 1: gather raw x (fp16), combine does both GEMMs ----
    gather64h_kernel<<<blocks((long long)N * 32, TB), TB>>>(N);
    combine1_kernel<<<blocks((long long)N * 64, TB), TB>>>(W1l, b1, x, W1r, N);

    // ---- layer 2: project 64->32 (fp16), gather, fused combine + layer-3 proj ----
    proj2h_kernel<<<blocks((long long)N * 32, TB), TB>>>(W2l, N);
    gather32h_kernel<<<blocks((long long)N * 16, TB), TB>>>(N);
    combine2_fused_kernel<<<blocks((long long)N * 32, TB), TB>>>(b2, W2r, W3l, W3r, N);

    // ---- layer 3: scalar gather + sigmoid ----
    gather1_final_kernel<<<blocks((long long)N * 32, TB), TB>>>(b3, out, N);
}